// round 6
// baseline (speedup 1.0000x reference)
#include <cuda_runtime.h>
#include <cuda_bf16.h>

#define BSZ 8
#define LEN 4096
#define DM  128   // d_model (M)
#define DS  128   // d_state (N)

#define TO 1024   // output tile (time) per CTA
#define TU 128    // input tile (time)
#define NT 128    // threads per CTA (conv) -> 4 warps, all SMSPs covered
#define RR 8      // output rows (l = t0 + tid + r*128) per thread

// -------- scratch (__device__ globals; no allocation allowed) --------
__device__ float g_xt[BSZ * DM * LEN];    // x transposed to (b, m, l)
__device__ float g_psum[DS * LEN];        // Psum[k, l]
__device__ float g_kern[DM * LEN];        // kernel[m, l]
__device__ float g_G[DM * DS];            // G = C @ B

using u64 = unsigned long long;
__device__ __forceinline__ void ffma2(u64 &d, u64 a, u64 b) {
    asm("fma.rn.f32x2 %0, %1, %2, %0;" : "+l"(d) : "l"(a), "l"(b));
}
__device__ __forceinline__ u64 pack2(float lo, float hi) {
    u64 r; asm("mov.b64 %0, {%1, %2};" : "=l"(r) : "f"(lo), "f"(hi)); return r;
}
__device__ __forceinline__ void unpack2(u64 v, float &lo, float &hi) {
    asm("mov.b64 {%0, %1}, %2;" : "=f"(lo), "=f"(hi) : "l"(v));
}

// -------- 1) transpose x (b,l,m) -> (b,m,l) --------
__global__ void transpose_kernel(const float* __restrict__ x) {
    __shared__ float tile[32][33];
    int b  = blockIdx.z;
    int l0 = blockIdx.x * 32;
    int m0 = blockIdx.y * 32;
    int tx = threadIdx.x, ty = threadIdx.y;
#pragma unroll
    for (int j = 0; j < 32; j += 8)
        tile[ty + j][tx] = x[(b * LEN + l0 + ty + j) * DM + m0 + tx];
    __syncthreads();
#pragma unroll
    for (int j = 0; j < 32; j += 8)
        g_xt[(b * DM + m0 + ty + j) * LEN + l0 + tx] = tile[tx][ty + j];
}

// -------- 2) Psum[k,l] = sum_{m'} exp(dt[m'] * Lam[k] * l) --------
__global__ void psum_kernel(const float* __restrict__ Lam,
                            const float* __restrict__ log_dt) {
    __shared__ float dt_s[DM];
    int k = blockIdx.x;
    int l = blockIdx.y * 128 + threadIdx.x;
    dt_s[threadIdx.x] = __expf(log_dt[threadIdx.x]);
    __syncthreads();
    float a = Lam[k] * (float)l;   // <= 0
    float s = 0.f;
#pragma unroll 8
    for (int mp = 0; mp < DM; ++mp)
        s += __expf(dt_s[mp] * a);
    g_psum[k * LEN + l] = s;
}

// -------- 3) G = C @ B --------
__global__ void gmat_kernel(const float* __restrict__ Bm,
                            const float* __restrict__ Cm) {
    __shared__ float c_s[DS];
    int m = blockIdx.x;
    int k = threadIdx.x;
    c_s[k] = Cm[m * DS + k];
    __syncthreads();
    float g = 0.f;
#pragma unroll 8
    for (int i = 0; i < DS; ++i)
        g = fmaf(c_s[i], Bm[i * DM + k], g);
    g_G[m * DS + k] = g;
}

// -------- 4) kernel[m,l] = sum_k G[m,k] * Psum[k,l] --------
// f32x2 over m-pairs; G pairs pre-duplicated in smem. grid (16, 32), block 128.
__global__ void __launch_bounds__(128) kern_kernel() {
    __shared__ u64 g2[4][DS];   // (G[m0+2h,k], G[m0+2h+1,k])
    const int m0 = blockIdx.x * 8;
    const int l  = blockIdx.y * 128 + threadIdx.x;
    const int k0 = threadIdx.x;
#pragma unroll
    for (int h = 0; h < 4; ++h)
        g2[h][k0] = pack2(g_G[(m0 + 2 * h) * DS + k0],
                          g_G[(m0 + 2 * h + 1) * DS + k0]);
    __syncthreads();
    u64 a[4] = {0ull, 0ull, 0ull, 0ull};
#pragma unroll 8
    for (int k = 0; k < DS; ++k) {
        float p = g_psum[k * LEN + l];
        u64 pv = pack2(p, p);
#pragma unroll
        for (int h = 0; h < 4; ++h)
            ffma2(a[h], g2[h][k], pv);
    }
#pragma unroll
    for (int h = 0; h < 4; ++h) {
        float lo, hi;
        unpack2(a[h], lo, hi);
        g_kern[(m0 + 2 * h) * LEN + l]     = lo;
        g_kern[(m0 + 2 * h + 1) * LEN + l] = hi;
    }
}

// -------- 5) causal conv + skip, f32x2 packed FMA --------
// 1D grid of 512: m = bid & 127, tt = 3 - bid/128 (heavy tiles first).
// 128 threads; each owns 8 output rows x 8 batches (4 f32x2 accs per row).
// Kernel taps pre-duplicated in smem as u64 pairs -> LDS.64, no per-tap MOV.
__global__ void __launch_bounds__(NT) conv_kernel(const float* __restrict__ Dv,
                                                  float* __restrict__ out) {
    __shared__ __align__(16) u64   k2_s[TO + TU];   // 9216 B
    __shared__ __align__(16) float x_s[TU * 10];    // 5120 B

    const int bid = blockIdx.x;
    const int m   = bid & (DM - 1);
    const int tt  = (LEN / TO - 1) - (bid >> 7);
    const int t0  = tt * TO;
    const int tid = threadIdx.x;

    u64 acc[RR][4];
#pragma unroll
    for (int r = 0; r < RR; ++r)
#pragma unroll
        for (int h = 0; h < 4; ++h) acc[r][h] = 0ull;

    const float* krow = g_kern + m * LEN;
    const int n_u = (t0 + TO) / TU;

    for (int ut = 0; ut < n_u; ++ut) {
        const int u0 = ut * TU;
        __syncthreads();
        const int j0 = t0 - u0 - (TU - 1);
#pragma unroll
        for (int ii = 0; ii < (TO + TU) / NT; ++ii) {   // 9
            int i = tid + ii * NT;
            int j = j0 + i;
            float kf = (j >= 0) ? krow[j] : 0.f;
            k2_s[i] = pack2(kf, kf);
        }
        {
            const float* xp = g_xt + m * LEN + u0 + tid;
#pragma unroll
            for (int b = 0; b < BSZ; ++b)
                x_s[tid * 10 + b] = xp[b * DM * LEN];
        }
        __syncthreads();

#pragma unroll 2
        for (int uj = 0; uj < TU; ++uj) {
            u64 xv[4];
            const float2* xp2 = (const float2*)(x_s + uj * 10);
#pragma unroll
            for (int h = 0; h < 4; ++h) {
                float2 v = xp2[h];
                xv[h] = pack2(v.x, v.y);
            }
#pragma unroll
            for (int r = 0; r < RR; ++r) {
                u64 kv = k2_s[tid + r * NT + (TU - 1) - uj];
#pragma unroll
                for (int h = 0; h < 4; ++h)
                    ffma2(acc[r][h], kv, xv[h]);
            }
        }
    }

    // epilogue: skip connection + store to (b, l, m)
    const float dv = Dv[m];
#pragma unroll
    for (int r = 0; r < RR; ++r) {
        int l = t0 + tid + r * NT;
#pragma unroll
        for (int h = 0; h < 4; ++h) {
            float lo, hi;
            unpack2(acc[r][h], lo, hi);
            int b0 = 2 * h, b1 = 2 * h + 1;
            float x0 = g_xt[(b0 * DM + m) * LEN + l];
            float x1 = g_xt[(b1 * DM + m) * LEN + l];
            out[(b0 * LEN + l) * DM + m] = fmaf(dv, x0, lo);
            out[(b1 * LEN + l) * DM + m] = fmaf(dv, x1, hi);
        }
    }
}

extern "C" void kernel_launch(void* const* d_in, const int* in_sizes, int n_in,
                              void* d_out, int out_size) {
    const float* x      = (const float*)d_in[0];  // (8, 4096, 128)
    const float* Lam    = (const float*)d_in[1];  // (128,)
    const float* Bm     = (const float*)d_in[2];  // (128, 128)
    const float* Cm     = (const float*)d_in[3];  // (128, 128)
    const float* Dv     = (const float*)d_in[4];  // (128,)
    const float* log_dt = (const float*)d_in[5];  // (128,)
    float* out = (float*)d_out;

    transpose_kernel<<<dim3(LEN / 32, DM / 32, BSZ), dim3(32, 8)>>>(x);
    psum_kernel<<<dim3(DS, LEN / 128), 128>>>(Lam, log_dt);
    gmat_kernel<<<DM, DS>>>(Bm, Cm);
    kern_kernel<<<dim3(DM / 8, LEN / 128), 128>>>();
    conv_kernel<<<(LEN / TO) * DM, NT>>>(Dv, out);
}